// round 17
// baseline (speedup 1.0000x reference)
#include <cuda_runtime.h>
#include <cuda_bf16.h>
#include <math.h>
#include <stdint.h>

// Problem constants
#define Bv   8
#define Nv   784
#define Cv   768
#define Hv   8
#define Dv   96
#define NNv  614656            // 784*784
#define BNNv 4917248           // B*N*N
#define BHND 4816896           // B*H*N*D = B*N*C
#define NN8  39337984          // B*H*N*N
#define WPN  589824            // 768*768
#define SCALEF 0.1020620726159657495f   // 96^-0.5
#define BN_EPS 1e-5

// ---------------- scratch (static device memory; no allocs allowed) -------
__device__ __align__(16) __nv_bfloat16 g_qhh[BHND], g_qhl[BHND];   // Q split (pre-scaled)
__device__ __align__(16) __nv_bfloat16 g_khh[BHND], g_khl[BHND];   // K split
__device__ float  g_vh[BHND];                                       // V fp32 (bh, m, d)
__device__ __align__(16) __nv_bfloat16 g_vth[BHND], g_vtl[BHND];   // V^T split (bh, d, m)
__device__ float  g_attn[NN8];                                      // logits (B,H,N,N)
__device__ __align__(16) __nv_bfloat16 g_a2h[NN8], g_a2l[NN8];     // mixed A split (B,O,N,N)
__device__ __align__(16) __nv_bfloat16 g_xch[BHND], g_xcl[BHND];   // xcat split (B,N,C)
__device__ __align__(16) __nv_bfloat16 g_wph[WPN], g_wpl[WPN];     // Wp split
__device__ float  g_colsum[Bv*Hv*Dv];
__device__ double g_stats[16];
__device__ float  g_bn[16];

// ---------------- zero stats ---------------------------------------------
__global__ void zero_stats_kernel() {
    int t = threadIdx.x;
    if (t < 16) g_stats[t] = 0.0;
}

// ---------------- split helpers ------------------------------------------
__device__ __forceinline__ void split1(float x, __nv_bfloat16& h, __nv_bfloat16& l) {
    h = __float2bfloat16_rn(x);
    l = __float2bfloat16_rn(x - __bfloat162float(h));
}
__device__ __forceinline__ void split2(float x, float y, uint32_t& hi, uint32_t& lo) {
    __nv_bfloat162 h2, l2;
    h2.x = __float2bfloat16_rn(x);
    h2.y = __float2bfloat16_rn(y);
    l2.x = __float2bfloat16_rn(x - __bfloat162float(h2.x));
    l2.y = __float2bfloat16_rn(y - __bfloat162float(h2.y));
    hi = *(uint32_t*)&h2;
    lo = *(uint32_t*)&l2;
}

// ---------------- per-token 3x3 conv QKV projection ----------------------
__global__ void __launch_bounds__(256) conv_qkv_kernel(
        const float* __restrict__ q,
        const float* __restrict__ k,
        const float* __restrict__ v,
        const float* __restrict__ Wq,
        const float* __restrict__ Wk,
        const float* __restrict__ Wv) {
    __shared__ float xs[768];
    __shared__ float ws[81];
    const int t     = blockIdx.x;          // token = b*N + n
    const int which = blockIdx.y;
    const float* in = (which == 0) ? q : (which == 1) ? k : v;
    const float* W  = (which == 0) ? Wq : (which == 1) ? Wk : Wv;
    const float mul = (which == 0) ? SCALEF : 1.0f;
    __nv_bfloat16* outh = (which == 0) ? g_qhh : g_khh;
    __nv_bfloat16* outl = (which == 0) ? g_qhl : g_khl;
    const int tid = threadIdx.x;

    const float* xin = in + (size_t)t * 768;
    for (int i = tid; i < 768; i += 256) xs[i] = xin[i];
    if (tid < 81) ws[tid] = W[tid];
    __syncthreads();

    const int b = t / Nv, n = t % Nv;
    #pragma unroll
    for (int r = 0; r < 3; r++) {
        const int c   = tid + 256 * r;
        const int co  = c >> 8;
        const int rem = c & 255;
        const int i   = rem >> 4, j = rem & 15;
        float acc = 0.f;
        #pragma unroll
        for (int ci = 0; ci < 3; ci++) {
            #pragma unroll
            for (int di = 0; di < 3; di++) {
                const int ii = i + di - 1;
                if (ii < 0 || ii > 15) continue;
                #pragma unroll
                for (int dj = 0; dj < 3; dj++) {
                    const int jj = j + dj - 1;
                    if (jj < 0 || jj > 15) continue;
                    acc += xs[ci * 256 + ii * 16 + jj] * ws[co * 27 + ci * 9 + di * 3 + dj];
                }
            }
        }
        const int h = c / 96, d = c % 96;
        const size_t idx = ((size_t)(b * Hv + h) * Nv + n) * Dv + d;
        if (which == 2) {
            g_vh[idx] = acc;
        } else {
            __nv_bfloat16 hh, ll;
            split1(acc * mul, hh, ll);
            outh[idx] = hh;
            outl[idx] = ll;
        }
    }
}

// ---------------- column sums of V ----------------------------------------
__global__ void __launch_bounds__(384) colsum_v_kernel() {
    __shared__ float part[4][96];
    const int bh   = blockIdx.x;
    const int d    = threadIdx.x % 96;
    const int slc  = threadIdx.x / 96;
    const float* vp = g_vh + (size_t)bh * Nv * Dv + d;
    float s = 0.f;
    for (int m = slc; m < Nv; m += 4) s += vp[(size_t)m * Dv];
    part[slc][d] = s;
    __syncthreads();
    if (slc == 0)
        g_colsum[bh * Dv + d] = part[0][d] + part[1][d] + part[2][d] + part[3][d];
}

// ---------------- transpose V + split: (bh,m,d) -> hi/lo (bh,d,m) ---------
__global__ void __launch_bounds__(256) transpose_v_kernel() {
    __shared__ float tile[32][33];
    const int bh = blockIdx.z;
    const int m0 = blockIdx.x * 32;
    const int d0 = blockIdx.y * 32;
    const float* src = g_vh + (size_t)bh * Nv * Dv;
    const size_t dbase = (size_t)bh * Dv * Nv;
    const int tx = threadIdx.x, ty = threadIdx.y;
    #pragma unroll
    for (int i = 0; i < 32; i += 8) {
        const int m = m0 + ty + i;
        tile[ty + i][tx] = (m < Nv) ? src[(size_t)m * Dv + d0 + tx] : 0.f;
    }
    __syncthreads();
    #pragma unroll
    for (int i = 0; i < 32; i += 8) {
        const int d = d0 + ty + i;
        const int m = m0 + tx;
        if (m < Nv) {
            __nv_bfloat16 hh, ll;
            split1(tile[tx][ty + i], hh, ll);
            g_vth[dbase + (size_t)d * Nv + m] = hh;
            g_vtl[dbase + (size_t)d * Nv + m] = ll;
        }
    }
}

// ---------------- split Wp into hi/lo -------------------------------------
__global__ void __launch_bounds__(256) split_wp_kernel(const float* __restrict__ Wp) {
    const int i = blockIdx.x * 256 + threadIdx.x;
    if (i < WPN) {
        __nv_bfloat16 hh, ll;
        split1(Wp[i], hh, ll);
        g_wph[i] = hh;
        g_wpl[i] = ll;
    }
}

// ---------------- cp.async helpers ----------------------------------------
__device__ __forceinline__ void cp16(void* dst, const void* src, int valid) {
    uint32_t s = (uint32_t)__cvta_generic_to_shared(dst);
    int sz = valid ? 16 : 0;
    asm volatile("cp.async.cg.shared.global [%0], [%1], 16, %2;\n"
                 :: "r"(s), "l"(src), "r"(sz));
}

__device__ __forceinline__ void mma_bf16(float* c, const uint32_t* a, const uint32_t* b) {
    asm volatile(
        "mma.sync.aligned.m16n8k16.row.col.f32.bf16.bf16.f32 "
        "{%0,%1,%2,%3}, {%4,%5,%6,%7}, {%8,%9}, {%0,%1,%2,%3};"
        : "+f"(c[0]), "+f"(c[1]), "+f"(c[2]), "+f"(c[3])
        : "r"(a[0]), "r"(a[1]), "r"(a[2]), "r"(a[3]), "r"(b[0]), "r"(b[1]));
}

#define LDSB 24   // smem row stride in bf16 (48B) — conflict-free frag loads

// ---------------- QK GEMM: 112x112 tile, 224 threads (7 warps x 16 rows) ---
// S = Qs * K^T, both operands 784xK=96 row-major pre-split. Zero tile waste.
__global__ void __launch_bounds__(224) mma7_qk_kernel() {
    __shared__ __align__(16) __nv_bfloat16 sm[2][4][112][LDSB];  // {Ah,Al,Bh,Bl}
    const int z = blockIdx.z;                    // bh
    const __nv_bfloat16* Ah = g_qhh + (size_t)z * Nv * Dv;
    const __nv_bfloat16* Al = g_qhl + (size_t)z * Nv * Dv;
    const __nv_bfloat16* Bh = g_khh + (size_t)z * Nv * Dv;
    const __nv_bfloat16* Bl = g_khl + (size_t)z * Nv * Dv;
    float* C = g_attn + (size_t)z * NNv;
    const int m0 = blockIdx.y * 112, n0 = blockIdx.x * 112;
    const int tid = threadIdx.x;
    const int w = tid >> 5, lane = tid & 31;
    const int g = lane >> 2, t4 = lane & 3;

    float acc[14][4];
    #pragma unroll
    for (int nf = 0; nf < 14; nf++)
        #pragma unroll
        for (int r = 0; r < 4; r++) acc[nf][r] = 0.f;

    // loader: 896 cp16 per stage (4 arrays x 112 rows x 2 k-halves)
    auto load_stage = [&](int stg, int kc) {
        #pragma unroll
        for (int i = 0; i < 4; i++) {
            const int u = i * 224 + tid;          // 0..895
            const int half = u & 1;
            const int rest = u >> 1;              // 0..447
            const int arr  = rest / 112;          // 0..3
            const int row  = rest % 112;
            const __nv_bfloat16* base = (arr == 0) ? Ah : (arr == 1) ? Al
                                       : (arr == 2) ? Bh : Bl;
            const int grow = ((arr < 2) ? m0 : n0) + row;   // always < 784
            const __nv_bfloat16* src = base + (size_t)grow * Dv + kc + half * 8;
            cp16(&sm[stg][arr][row][half * 8], src, 1);
        }
    };

    load_stage(0, 0);
    asm volatile("cp.async.commit_group;\n");

    const int nIter = Dv / 16;                    // 6
    for (int it = 0; it < nIter; it++) {
        asm volatile("cp.async.wait_group 0;\n");
        __syncthreads();
        if (it + 1 < nIter) {
            load_stage((it + 1) & 1, (it + 1) * 16);
            asm volatile("cp.async.commit_group;\n");
        }

        const int st = it & 1;
        uint32_t aH[4], aL[4], bH[14][2], bL[14][2];
        {
            const int r0 = w * 16 + g;
            const uint32_t* h0 = (const uint32_t*)&sm[st][0][r0][0];
            const uint32_t* h1 = (const uint32_t*)&sm[st][0][r0 + 8][0];
            const uint32_t* l0 = (const uint32_t*)&sm[st][1][r0][0];
            const uint32_t* l1 = (const uint32_t*)&sm[st][1][r0 + 8][0];
            aH[0] = h0[t4];     aH[1] = h1[t4];
            aH[2] = h0[t4 + 4]; aH[3] = h1[t4 + 4];
            aL[0] = l0[t4];     aL[1] = l1[t4];
            aL[2] = l0[t4 + 4]; aL[3] = l1[t4 + 4];
        }
        #pragma unroll
        for (int nf = 0; nf < 14; nf++) {
            const int rb = nf * 8 + g;
            const uint32_t* h = (const uint32_t*)&sm[st][2][rb][0];
            const uint32_t* l = (const uint32_t*)&sm[st][3][rb][0];
            bH[nf][0] = h[t4]; bH[nf][1] = h[t4 + 4];
            bL[nf][0] = l[t4]; bL[nf][1] = l[t4 + 4];
        }

        #pragma unroll
        for (int nf = 0; nf < 14; nf++) mma_bf16(acc[nf], aH, bH[nf]);
        #pragma unroll
        for (int nf = 0; nf < 14; nf++) mma_bf16(acc[nf], aH, bL[nf]);
        #pragma unroll
        for (int nf = 0; nf < 14; nf++) mma_bf16(acc[nf], aL, bH[nf]);
    }

    // epilogue (all rows/cols valid: 7*112 = 784 exact)
    const int r0 = m0 + w * 16 + g;
    const int r1 = r0 + 8;
    #pragma unroll
    for (int nf = 0; nf < 14; nf++) {
        const int col = n0 + nf * 8 + 2 * t4;
        float2 v0; v0.x = acc[nf][0]; v0.y = acc[nf][1];
        float2 v1; v1.x = acc[nf][2]; v1.y = acc[nf][3];
        *(float2*)(C + (size_t)r0 * Nv + col) = v0;
        *(float2*)(C + (size_t)r1 * Nv + col) = v1;
    }
}

// ---------------- AV GEMM: 112x96 tile, 224 threads (7 warps x 16 rows) ----
// xcat <- a_o * (A2 @ V) + c_o * colsum; A2 784x784, V^T 96x784. Zero waste.
__global__ void __launch_bounds__(224) mma7_av_kernel() {
    __shared__ __align__(16) __nv_bfloat16 smA[2][2][112][LDSB];
    __shared__ __align__(16) __nv_bfloat16 smB[2][2][96][LDSB];
    const int z = blockIdx.z;                    // bh = b*8 + o
    const __nv_bfloat16* Ah = g_a2h + (size_t)z * NNv;
    const __nv_bfloat16* Al = g_a2l + (size_t)z * NNv;
    const __nv_bfloat16* Bh = g_vth + (size_t)z * Dv * Nv;
    const __nv_bfloat16* Bl = g_vtl + (size_t)z * Dv * Nv;
    const int m0 = blockIdx.y * 112;
    const int tid = threadIdx.x;
    const int w = tid >> 5, lane = tid & 31;
    const int g = lane >> 2, t4 = lane & 3;

    float acc[12][4];
    #pragma unroll
    for (int nf = 0; nf < 12; nf++)
        #pragma unroll
        for (int r = 0; r < 4; r++) acc[nf][r] = 0.f;

    // loader: 832 cp16 per stage (A: 448, B: 384)
    auto load_stage = [&](int stg, int kc) {
        #pragma unroll
        for (int i = 0; i < 4; i++) {
            const int u = i * 224 + tid;
            if (u >= 832) break;
            if (u < 448) {
                const int half = u & 1;
                const int rest = u >> 1;          // 0..223
                const int part = rest / 112;
                const int row  = rest % 112;
                const __nv_bfloat16* src =
                    (part ? Al : Ah) + (size_t)(m0 + row) * Nv + kc + half * 8;
                cp16(&smA[stg][part][row][half * 8], src, 1);
            } else {
                const int vv = u - 448;
                const int half = vv & 1;
                const int rest = vv >> 1;         // 0..191
                const int part = rest / 96;
                const int row  = rest % 96;
                const __nv_bfloat16* src =
                    (part ? Bl : Bh) + (size_t)row * Nv + kc + half * 8;
                cp16(&smB[stg][part][row][half * 8], src, 1);
            }
        }
    };

    load_stage(0, 0);
    asm volatile("cp.async.commit_group;\n");

    const int nIter = Nv / 16;                    // 49
    for (int it = 0; it < nIter; it++) {
        asm volatile("cp.async.wait_group 0;\n");
        __syncthreads();
        if (it + 1 < nIter) {
            load_stage((it + 1) & 1, (it + 1) * 16);
            asm volatile("cp.async.commit_group;\n");
        }

        const int st = it & 1;
        uint32_t aH[4], aL[4], bH[12][2], bL[12][2];
        {
            const int r0 = w * 16 + g;
            const uint32_t* h0 = (const uint32_t*)&smA[st][0][r0][0];
            const uint32_t* h1 = (const uint32_t*)&smA[st][0][r0 + 8][0];
            const uint32_t* l0 = (const uint32_t*)&smA[st][1][r0][0];
            const uint32_t* l1 = (const uint32_t*)&smA[st][1][r0 + 8][0];
            aH[0] = h0[t4];     aH[1] = h1[t4];
            aH[2] = h0[t4 + 4]; aH[3] = h1[t4 + 4];
            aL[0] = l0[t4];     aL[1] = l1[t4];
            aL[2] = l0[t4 + 4]; aL[3] = l1[t4 + 4];
        }
        #pragma unroll
        for (int nf = 0; nf < 12; nf++) {
            const int rb = nf * 8 + g;
            const uint32_t* h = (const uint32_t*)&smB[st][0][rb][0];
            const uint32_t* l = (const uint32_t*)&smB[st][1][rb][0];
            bH[nf][0] = h[t4]; bH[nf][1] = h[t4 + 4];
            bL[nf][0] = l[t4]; bL[nf][1] = l[t4 + 4];
        }

        #pragma unroll
        for (int nf = 0; nf < 12; nf++) mma_bf16(acc[nf], aH, bH[nf]);
        #pragma unroll
        for (int nf = 0; nf < 12; nf++) mma_bf16(acc[nf], aH, bL[nf]);
        #pragma unroll
        for (int nf = 0; nf < 12; nf++) mma_bf16(acc[nf], aL, bH[nf]);
    }

    // epilogue: BN affine + colsum, split-write into xcat (all indices valid)
    const int b = z >> 3, o = z & 7;
    const float a_s = g_bn[o];
    const float c_s = g_bn[8 + o];
    const size_t xbase = (size_t)b * Nv * Cv + o * Dv;
    const int r0 = m0 + w * 16 + g;
    const int r1 = r0 + 8;
    #pragma unroll
    for (int nf = 0; nf < 12; nf++) {
        const int col = nf * 8 + 2 * t4;          // < 96
        const float cxs = c_s * g_colsum[z * Dv + col];
        const float cys = c_s * g_colsum[z * Dv + col + 1];
        uint32_t hi, lo;
        split2(a_s * acc[nf][0] + cxs, a_s * acc[nf][1] + cys, hi, lo);
        *(uint32_t*)(g_xch + xbase + (size_t)r0 * Cv + col) = hi;
        *(uint32_t*)(g_xcl + xbase + (size_t)r0 * Cv + col) = lo;
        split2(a_s * acc[nf][2] + cxs, a_s * acc[nf][3] + cys, hi, lo);
        *(uint32_t*)(g_xch + xbase + (size_t)r1 * Cv + col) = hi;
        *(uint32_t*)(g_xcl + xbase + (size_t)r1 * Cv + col) = lo;
    }
}

// ---------------- 128x128-tile bf16-split GEMM (proj: exact tiling) -------
__global__ void __launch_bounds__(256) mma4_plain_kernel(
        const __nv_bfloat16* __restrict__ Ah, const __nv_bfloat16* __restrict__ Al,
        const __nv_bfloat16* __restrict__ Bh, const __nv_bfloat16* __restrict__ Bl,
        float* __restrict__ C,
        int M, int Nn, int K, int lda, int ldb, int ldc,
        long sA, long sB, long sC, const float* __restrict__ bias) {
    extern __shared__ __nv_bfloat16 dsm4[];
    __nv_bfloat16 (*sm)[4][128][LDSB] = (__nv_bfloat16 (*)[4][128][LDSB])dsm4;

    const int z = blockIdx.z;
    Ah += (size_t)z * sA; Al += (size_t)z * sA;
    Bh += (size_t)z * sB; Bl += (size_t)z * sB;
    C  += (size_t)z * sC;
    const int m0 = blockIdx.y * 128, n0 = blockIdx.x * 128;
    const int tid  = threadIdx.x;
    const int warp = tid >> 5, lane = tid & 31;
    const int g = lane >> 2, t4 = lane & 3;
    const int wm = (warp & 1) * 64, wn = (warp >> 1) * 32;

    float acc[4][4][4];
    #pragma unroll
    for (int mf = 0; mf < 4; mf++)
        #pragma unroll
        for (int nf = 0; nf < 4; nf++)
            #pragma unroll
            for (int r = 0; r < 4; r++) acc[mf][nf][r] = 0.f;

    const int nIter = K / 16;
    auto load_stage = [&](int stg, int kc) {
        #pragma unroll
        for (int i = 0; i < 4; i++) {
            const int idx = i * 256 + tid;
            const int arr = idx >> 8;
            const int rem = idx & 255;
            const int row = rem >> 1, hf = rem & 1;
            const __nv_bfloat16* base;
            int grow, valid, ld;
            if (arr < 2) {
                grow = m0 + row; valid = grow < M; ld = lda;
                base = arr ? Al : Ah;
            } else {
                grow = n0 + row; valid = grow < Nn; ld = ldb;
                base = (arr == 3) ? Bl : Bh;
            }
            const __nv_bfloat16* src = base + (size_t)(valid ? grow : 0) * ld + kc + hf * 8;
            cp16(&sm[stg][arr][row][hf * 8], src, valid);
        }
    };

    load_stage(0, 0);
    asm volatile("cp.async.commit_group;\n");

    for (int it = 0; it < nIter; it++) {
        asm volatile("cp.async.wait_group 0;\n");
        __syncthreads();
        if (it + 1 < nIter) {
            load_stage((it + 1) & 1, (it + 1) * 16);
            asm volatile("cp.async.commit_group;\n");
        }

        const int st = it & 1;
        uint32_t aH[4][4], aL[4][4], bH[4][2], bL[4][2];
        #pragma unroll
        for (int mf = 0; mf < 4; mf++) {
            const int r0 = wm + mf * 16 + g;
            const uint32_t* h0 = (const uint32_t*)&sm[st][0][r0][0];
            const uint32_t* h1 = (const uint32_t*)&sm[st][0][r0 + 8][0];
            const uint32_t* l0 = (const uint32_t*)&sm[st][1][r0][0];
            const uint32_t* l1 = (const uint32_t*)&sm[st][1][r0 + 8][0];
            aH[mf][0] = h0[t4];     aH[mf][1] = h1[t4];
            aH[mf][2] = h0[t4 + 4]; aH[mf][3] = h1[t4 + 4];
            aL[mf][0] = l0[t4];     aL[mf][1] = l1[t4];
            aL[mf][2] = l0[t4 + 4]; aL[mf][3] = l1[t4 + 4];
        }
        #pragma unroll
        for (int nf = 0; nf < 4; nf++) {
            const int rb = wn + nf * 8 + g;
            const uint32_t* h = (const uint32_t*)&sm[st][2][rb][0];
            const uint32_t* l = (const uint32_t*)&sm[st][3][rb][0];
            bH[nf][0] = h[t4]; bH[nf][1] = h[t4 + 4];
            bL[nf][0] = l[t4]; bL[nf][1] = l[t4 + 4];
        }

        #pragma unroll
        for (int mf = 0; mf < 4; mf++)
            #pragma unroll
            for (int nf = 0; nf < 4; nf++)
                mma_bf16(acc[mf][nf], aH[mf], bH[nf]);
        #pragma unroll
        for (int mf = 0; mf < 4; mf++)
            #pragma unroll
            for (int nf = 0; nf < 4; nf++)
                mma_bf16(acc[mf][nf], aH[mf], bL[nf]);
        #pragma unroll
        for (int mf = 0; mf < 4; mf++)
            #pragma unroll
            for (int nf = 0; nf < 4; nf++)
                mma_bf16(acc[mf][nf], aL[mf], bH[nf]);
    }

    #pragma unroll
    for (int mf = 0; mf < 4; mf++) {
        #pragma unroll
        for (int nf = 0; nf < 4; nf++) {
            const int col = n0 + wn + nf * 8 + 2 * t4;
            if (col >= Nn) continue;
            float bx = 0.f, by = 0.f;
            if (bias) {
                const float2 bb = *(const float2*)(bias + col);
                bx = bb.x; by = bb.y;
            }
            const int r0 = m0 + wm + mf * 16 + g;
            if (r0 < M) {
                float2 vv; vv.x = acc[mf][nf][0] + bx; vv.y = acc[mf][nf][1] + by;
                *(float2*)(C + (size_t)r0 * ldc + col) = vv;
            }
            const int r1 = r0 + 8;
            if (r1 < M) {
                float2 vv; vv.x = acc[mf][nf][2] + bx; vv.y = acc[mf][nf][3] + by;
                *(float2*)(C + (size_t)r1 * ldc + col) = vv;
            }
        }
    }
}
#define MMA4_SMEM (2 * 4 * 128 * LDSB * 2)   // 49152 bytes

// ---------------- fused softmax + cross-head mix + BN stats ---------------
__global__ void __launch_bounds__(256) softmax_mix_stats_kernel(
        const float* __restrict__ Wre,
        const float* __restrict__ bre) {
    __shared__ float smx[8][Nv];
    __shared__ float sW[64];
    __shared__ float sb[8];
    __shared__ float part[8][16];
    const int bn  = blockIdx.x;           // b*Nv + n
    const int b   = bn / Nv, n = bn % Nv;
    const int tid = threadIdx.x;
    const int w   = tid >> 5, lane = tid & 31;
    if (tid < 64) sW[tid] = Wre[tid];
    if (tid < 8)  sb[tid] = bre[tid];

    // warp-per-head softmax
    const float* src = g_attn + ((size_t)(b * 8 + w) * Nv + n) * Nv;
    float lmax = -1e30f;
    for (int i = lane; i < Nv; i += 32) {
        const float vv = src[i];
        smx[w][i] = vv;
        lmax = fmaxf(lmax, vv);
    }
    #pragma unroll
    for (int s = 16; s; s >>= 1) lmax = fmaxf(lmax, __shfl_xor_sync(0xffffffffu, lmax, s));
    float lsum = 0.f;
    for (int i = lane; i < Nv; i += 32) {
        const float e = __expf(smx[w][i] - lmax);
        smx[w][i] = e;
        lsum += e;
    }
    #pragma unroll
    for (int s = 16; s; s >>= 1) lsum += __shfl_xor_sync(0xffffffffu, lsum, s);
    const float inv = 1.f / lsum;
    for (int i = lane; i < Nv; i += 32) smx[w][i] *= inv;
    __syncthreads();

    // per-thread analytic means
    float mu[8];
    #pragma unroll
    for (int o = 0; o < 8; o++) {
        float s = 0.f;
        #pragma unroll
        for (int h = 0; h < 8; h++) s += sW[o * 8 + h];
        mu[o] = s * (1.0f / (float)Nv) + sb[o];
    }

    // mix + stats + packed split-write (m pairs)
    const size_t obase = (size_t)b * Hv * NNv + (size_t)n * Nv;
    float sd[8], sq[8];
    #pragma unroll
    for (int o = 0; o < 8; o++) { sd[o] = 0.f; sq[o] = 0.f; }
    for (int mp = tid; mp < Nv / 2; mp += 256) {
        const int m = mp * 2;
        float p0[8], p1[8];
        #pragma unroll
        for (int h = 0; h < 8; h++) { p0[h] = smx[h][m]; p1[h] = smx[h][m + 1]; }
        #pragma unroll
        for (int o = 0; o < 8; o++) {
            float a0 = sb[o], a1 = sb[o];
            #pragma unroll
            for (int h = 0; h < 8; h++) {
                a0 += sW[o * 8 + h] * p0[h];
                a1 += sW[o * 8 + h] * p1[h];
            }
            uint32_t hi, lo;
            split2(a0, a1, hi, lo);
            *(uint32_t*)(g_a2h + obase + (size_t)o * NNv + m) = hi;
            *(uint32_t*)(g_a2l + obase + (size_t)o * NNv + m) = lo;
            const float d0 = a0 - mu[o];
            const float d1 = a1 - mu[o];
            sd[o] += d0 + d1;
            sq[o] += d0 * d0 + d1 * d1;
        }
    }
    #pragma unroll
    for (int o = 0; o < 8; o++) {
        #pragma unroll
        for (int s = 16; s; s >>= 1) {
            sd[o] += __shfl_xor_sync(0xffffffffu, sd[o], s);
            sq[o] += __shfl_xor_sync(0xffffffffu, sq[o], s);
        }
    }
    if (lane == 0) {
        #pragma unroll
        for (int o = 0; o < 8; o++) {
            part[w][o]     = sd[o];
            part[w][8 + o] = sq[o];
        }
    }
    __syncthreads();
    if (tid < 16) {
        float s = 0.f;
        #pragma unroll
        for (int ww = 0; ww < 8; ww++) s += part[ww][tid];
        atomicAdd(&g_stats[tid], (double)s);
    }
}

// ---------------- finalize BN scalars -------------------------------------
__global__ void bn_finalize_kernel(const float* __restrict__ Wre,
                                   const float* __restrict__ bre,
                                   const float* __restrict__ gamma,
                                   const float* __restrict__ beta) {
    const int o = threadIdx.x;
    if (o >= 8) return;
    const double cnt = (double)BNNv;
    float s = 0.f;
    #pragma unroll
    for (int h = 0; h < 8; h++) s += Wre[o * 8 + h];
    const double mu   = (double)s / (double)Nv + (double)bre[o];
    const double sd   = g_stats[o];
    const double sq   = g_stats[8 + o];
    const double mean = mu + sd / cnt;
    const double var  = sq / cnt - (sd / cnt) * (sd / cnt);
    const float a = gamma[o] * (float)(1.0 / sqrt(var + (double)BN_EPS));
    const float c = beta[o] - a * (float)mean;
    g_bn[o]     = a;
    g_bn[8 + o] = c;
}

// ---------------- launch ---------------------------------------------------
extern "C" void kernel_launch(void* const* d_in, const int* in_sizes, int n_in,
                              void* d_out, int out_size) {
    const float* q     = (const float*)d_in[0];
    const float* k     = (const float*)d_in[1];
    const float* v     = (const float*)d_in[2];
    const float* Wq    = (const float*)d_in[3];
    const float* Wk    = (const float*)d_in[4];
    const float* Wv    = (const float*)d_in[5];
    const float* Wre   = (const float*)d_in[6];
    const float* bre   = (const float*)d_in[7];
    const float* gamma = (const float*)d_in[8];
    const float* beta  = (const float*)d_in[9];
    const float* Wp    = (const float*)d_in[10];
    const float* bp    = (const float*)d_in[11];
    float* out = (float*)d_out;

    void *pxch, *pxcl, *pwph, *pwpl;
    cudaGetSymbolAddress(&pxch,  g_xch);
    cudaGetSymbolAddress(&pxcl,  g_xcl);
    cudaGetSymbolAddress(&pwph,  g_wph);
    cudaGetSymbolAddress(&pwpl,  g_wpl);

    cudaFuncSetAttribute(mma4_plain_kernel,
                         cudaFuncAttributeMaxDynamicSharedMemorySize, MMA4_SMEM);

    zero_stats_kernel<<<1, 32>>>();
    conv_qkv_kernel<<<dim3(Bv * Nv, 3), 256>>>(q, k, v, Wq, Wk, Wv);
    colsum_v_kernel<<<Bv * Hv, 384>>>();
    transpose_v_kernel<<<dim3(25, 3, 64), dim3(32, 8)>>>();
    split_wp_kernel<<<(WPN + 255) / 256, 256>>>(Wp);

    // S = Qs Kh^T — 112x112 tiles, zero waste
    mma7_qk_kernel<<<dim3(7, 7, Bv * Hv), 224>>>();

    softmax_mix_stats_kernel<<<Bv * Nv, 256>>>(Wre, bre);
    bn_finalize_kernel<<<1, 8>>>(Wre, bre, gamma, beta);

    // AV — 112x96 tiles, zero waste
    mma7_av_kernel<<<dim3(1, 7, Bv * Hv), 224>>>();

    // out = xcat @ Wp^T + bp — 128x128 tiles (exact for 6272x768)
    mma4_plain_kernel<<<dim3(6, 49, 1), 256, MMA4_SMEM>>>(
        (const __nv_bfloat16*)pxch, (const __nv_bfloat16*)pxcl,
        (const __nv_bfloat16*)pwph, (const __nv_bfloat16*)pwpl,
        out,
        Bv * Nv, Cv, Cv, Cv, Cv, Cv,
        0L, 0L, 0L,
        bp);
}